// round 2
// baseline (speedup 1.0000x reference)
#include <cuda_runtime.h>
#include <cstdint>
#include <math.h>

// ---------------------------------------------------------------------------
// MultiHeadSINDyAttention
//   N=4, L=2048, E_Q=E_TOTAL=512, H=8, E_HEAD=64, FORECAST=8
//
// Pipeline (algebraically fused):
//   qkv  = query @ Wqkv + bqkv                      (GEMM 8192x1536x512)
//   attn = causal_flash_attention(q,k,v)            (32 heads, 2048x64)
//   M_h  = I + Xi_h - Xi_h^T ;  W_eff[f] = M_h^{f+1} @ Wo_h   (tiny)
//   out[b,f,s,:] = attn_concat[b,s,:] @ W_eff[f] + bo         (8 GEMMs 8192x512x512)
// ---------------------------------------------------------------------------

namespace {
constexpr int BATCH = 4;
constexpr int SEQ   = 2048;
constexpr int E     = 512;
constexpr int E3    = 1536;
constexpr int H     = 8;
constexpr int D     = 64;
constexpr int F     = 8;
constexpr int MROWS = BATCH * SEQ;   // 8192
}

// scratch (device globals: no allocation allowed in kernel_launch)
__device__ float g_qkv[MROWS * E3];   // [8192,1536]
__device__ float g_attn[MROWS * E];   // [8192,512]  concat-head attention output
__device__ float g_weff[F * E * E];   // [8][512][512]  M^{f+1} @ Wo (head-block rows)

// ---------------------------------------------------------------------------
// 128x128 tile, BK=8, double-buffered SGEMM. 256 threads, 8x8 micro-tile.
// MODE 0: C[r,c] = A @ B + bias,  A=param (query), B=param (Wqkv), C=g_qkv, N=1536
// MODE 1: A=g_attn, B=g_weff + z*E*E, C=out with [b,f,s,e] row remap, N=512
// ---------------------------------------------------------------------------
template<int MODE>
__global__ __launch_bounds__(256, 2)
void sgemm128(const float* __restrict__ Ap, const float* __restrict__ Bp,
              const float* __restrict__ bias, float* __restrict__ Cp)
{
    constexpr int N = (MODE == 0) ? E3 : E;
    constexpr int K = E;
    const float* A = (MODE == 0) ? Ap : g_attn;
    const float* B = (MODE == 0) ? Bp : (g_weff + (size_t)blockIdx.z * E * E);

    __shared__ float As[2][8][128];   // [k][m] (A stored transposed)
    __shared__ float Bs[2][8][128];   // [k][n]

    const int tid = threadIdx.x;
    const int bm = blockIdx.y, bn = blockIdx.x;

    const int arow = tid >> 1;              // 0..127
    const int akv  = (tid & 1) * 4;         // 0 or 4
    const int brow = tid >> 5;              // 0..7
    const int bcol = (tid & 31) * 4;        // 0..124

    const float* Aptr = A + (size_t)(bm * 128 + arow) * K + akv;
    const float* Bptr = B + (size_t)brow * N + bn * 128 + bcol;

    const int tx = tid & 15, ty = tid >> 4;

    float acc[8][8];
    #pragma unroll
    for (int i = 0; i < 8; i++)
        #pragma unroll
        for (int j = 0; j < 8; j++) acc[i][j] = 0.0f;

    // prologue: tile 0
    float4 av = *(const float4*)Aptr;
    float4 bv = *(const float4*)Bptr;
    As[0][akv + 0][arow] = av.x;
    As[0][akv + 1][arow] = av.y;
    As[0][akv + 2][arow] = av.z;
    As[0][akv + 3][arow] = av.w;
    *(float4*)&Bs[0][brow][bcol] = bv;
    __syncthreads();

    const int nk = K >> 3;   // 64
    for (int kt = 0; kt < nk; kt++) {
        const int buf = kt & 1;
        if (kt + 1 < nk) {
            av = *(const float4*)(Aptr + (kt + 1) * 8);
            bv = *(const float4*)(Bptr + (size_t)(kt + 1) * 8 * N);
        }
        #pragma unroll
        for (int kk = 0; kk < 8; kk++) {
            float a[8], b[8];
            *(float4*)(a)     = *(const float4*)&As[buf][kk][ty * 4];
            *(float4*)(a + 4) = *(const float4*)&As[buf][kk][64 + ty * 4];
            *(float4*)(b)     = *(const float4*)&Bs[buf][kk][tx * 4];
            *(float4*)(b + 4) = *(const float4*)&Bs[buf][kk][64 + tx * 4];
            #pragma unroll
            for (int i = 0; i < 8; i++)
                #pragma unroll
                for (int j = 0; j < 8; j++)
                    acc[i][j] += a[i] * b[j];
        }
        if (kt + 1 < nk) {
            const int nb = buf ^ 1;
            As[nb][akv + 0][arow] = av.x;
            As[nb][akv + 1][arow] = av.y;
            As[nb][akv + 2][arow] = av.z;
            As[nb][akv + 3][arow] = av.w;
            *(float4*)&Bs[nb][brow][bcol] = bv;
            __syncthreads();
        }
    }

    // epilogue
    float bvals[8];
    #pragma unroll
    for (int j = 0; j < 8; j++) {
        int col = bn * 128 + ((j < 4) ? tx * 4 + j : 64 + tx * 4 + (j - 4));
        bvals[j] = bias[col];
    }
    #pragma unroll
    for (int i = 0; i < 8; i++) {
        const int r = bm * 128 + ((i < 4) ? ty * 4 + i : 64 + ty * 4 + (i - 4));
        float4 v0 = make_float4(acc[i][0] + bvals[0], acc[i][1] + bvals[1],
                                acc[i][2] + bvals[2], acc[i][3] + bvals[3]);
        float4 v1 = make_float4(acc[i][4] + bvals[4], acc[i][5] + bvals[5],
                                acc[i][6] + bvals[6], acc[i][7] + bvals[7]);
        if (MODE == 0) {
            float* cp = g_qkv + (size_t)r * N + bn * 128;
            *(float4*)(cp + tx * 4)      = v0;
            *(float4*)(cp + 64 + tx * 4) = v1;
        } else {
            const int bb = r >> 11;          // row / 2048
            const int ss = r & 2047;
            float* cp = Cp + (((size_t)bb * F + blockIdx.z) * SEQ + ss) * E + bn * 128;
            *(float4*)(cp + tx * 4)      = v0;
            *(float4*)(cp + 64 + tx * 4) = v1;
        }
    }
}

// ---------------------------------------------------------------------------
// Causal flash attention. One block per (q-block of 64 rows, head, batch).
// 256 threads as 16x16; thread owns a 4x4 S-tile and 4x4 O-tile.
// Q,K stored d-major (transposed) in smem -> float4 reads in QK^T.
// P overlays the K tile (used in disjoint phases) -> exactly 48KB static smem.
// ---------------------------------------------------------------------------
__global__ __launch_bounds__(256)
void flash64()
{
    __shared__ float Qt[64][64];   // [d][row], pre-scaled by 1/8
    __shared__ float KtPs[64][64]; // phase 1: Kt [d][col]; phase 2: P [row][col]
    __shared__ float Vs[64][64];   // [col(key)][d]

    const int qb = blockIdx.x, h = blockIdx.y, b = blockIdx.z;
    const int tid = threadIdx.x, tx = tid & 15, ty = tid >> 4;
    const unsigned FULL = 0xffffffffu;
    const float* base = g_qkv + (size_t)b * SEQ * E3 + h * D;

    #pragma unroll
    for (int l = 0; l < 4; l++) {
        int idx = tid + l * 256;
        int r = idx >> 4, v = (idx & 15) * 4;
        float4 t = *(const float4*)(base + (size_t)(qb * 64 + r) * E3 + v);
        Qt[v + 0][r] = t.x * 0.125f;
        Qt[v + 1][r] = t.y * 0.125f;
        Qt[v + 2][r] = t.z * 0.125f;
        Qt[v + 3][r] = t.w * 0.125f;
    }

    float mi[4], li[4], o[4][4];
    #pragma unroll
    for (int i = 0; i < 4; i++) {
        mi[i] = -1e30f;
        li[i] = 0.0f;
        #pragma unroll
        for (int j = 0; j < 4; j++) o[i][j] = 0.0f;
    }

    for (int jb = 0; jb <= qb; jb++) {
        __syncthreads();   // protect smem from previous iteration's readers
        #pragma unroll
        for (int l = 0; l < 4; l++) {
            int idx = tid + l * 256;
            int r = idx >> 4, v = (idx & 15) * 4;
            const float* rp = base + (size_t)(jb * 64 + r) * E3;
            float4 k4 = *(const float4*)(rp + 512 + v);
            KtPs[v + 0][r] = k4.x;
            KtPs[v + 1][r] = k4.y;
            KtPs[v + 2][r] = k4.z;
            KtPs[v + 3][r] = k4.w;
            float4 v4 = *(const float4*)(rp + 1024 + v);
            *(float4*)&Vs[r][v] = v4;
        }
        __syncthreads();

        float s[4][4];
        #pragma unroll
        for (int i = 0; i < 4; i++)
            #pragma unroll
            for (int j = 0; j < 4; j++) s[i][j] = 0.0f;

        #pragma unroll 8
        for (int kk = 0; kk < 64; kk++) {
            float a[4], bb[4];
            *(float4*)a  = *(const float4*)&Qt[kk][ty * 4];
            *(float4*)bb = *(const float4*)&KtPs[kk][tx * 4];
            #pragma unroll
            for (int i = 0; i < 4; i++)
                #pragma unroll
                for (int j = 0; j < 4; j++)
                    s[i][j] += a[i] * bb[j];
        }

        if (jb == qb) {   // causal mask on the diagonal block
            #pragma unroll
            for (int i = 0; i < 4; i++)
                #pragma unroll
                for (int j = 0; j < 4; j++)
                    if (tx * 4 + j > ty * 4 + i) s[i][j] = -1e30f;
        }

        __syncthreads();   // everyone done reading Kt before P overlays it

        #pragma unroll
        for (int i = 0; i < 4; i++) {
            float mx = fmaxf(fmaxf(s[i][0], s[i][1]), fmaxf(s[i][2], s[i][3]));
            #pragma unroll
            for (int off = 8; off; off >>= 1)
                mx = fmaxf(mx, __shfl_xor_sync(FULL, mx, off));
            float mn = fmaxf(mi[i], mx);
            float sc = __expf(mi[i] - mn);
            float rs = 0.0f;
            #pragma unroll
            for (int j = 0; j < 4; j++) {
                float p = __expf(s[i][j] - mn);
                s[i][j] = p;
                rs += p;
            }
            #pragma unroll
            for (int off = 8; off; off >>= 1)
                rs += __shfl_xor_sync(FULL, rs, off);
            li[i] = li[i] * sc + rs;
            mi[i] = mn;
            #pragma unroll
            for (int j = 0; j < 4; j++) o[i][j] *= sc;
            KtPs[ty * 4 + i][tx * 4 + 0] = s[i][0];
            KtPs[ty * 4 + i][tx * 4 + 1] = s[i][1];
            KtPs[ty * 4 + i][tx * 4 + 2] = s[i][2];
            KtPs[ty * 4 + i][tx * 4 + 3] = s[i][3];
        }
        __syncthreads();

        #pragma unroll 8
        for (int kk = 0; kk < 64; kk++) {
            float4 b4 = *(const float4*)&Vs[kk][tx * 4];
            #pragma unroll
            for (int i = 0; i < 4; i++) {
                float a = KtPs[ty * 4 + i][kk];
                o[i][0] += a * b4.x;
                o[i][1] += a * b4.y;
                o[i][2] += a * b4.z;
                o[i][3] += a * b4.w;
            }
        }
    }

    float* op = g_attn + ((size_t)b * SEQ + qb * 64) * E + h * D;
    #pragma unroll
    for (int i = 0; i < 4; i++) {
        float inv = 1.0f / li[i];
        float4 v = make_float4(o[i][0] * inv, o[i][1] * inv,
                               o[i][2] * inv, o[i][3] * inv);
        *(float4*)(op + (size_t)(ty * 4 + i) * E + tx * 4) = v;
    }
}

// ---------------------------------------------------------------------------
// W_eff[f] = M_h^{f+1} @ Wo_h, via recurrence W_{f+1} = M @ W_f.
// Grid (col-chunk of 128, head). Column-independent, so chunks parallelize.
// ---------------------------------------------------------------------------
__global__ __launch_bounds__(256)
void weff_kernel(const float* __restrict__ Xi, const float* __restrict__ Wo)
{
    __shared__ float Ms[64][64];
    __shared__ float Wc[64][128];
    const int h = blockIdx.y, ch = blockIdx.x;
    const int tid = threadIdx.x;
    const float* xh = Xi + h * 64 * 64;

    #pragma unroll
    for (int l = 0; l < 16; l++) {
        int idx = tid + l * 256;
        int r = idx >> 6, c = idx & 63;
        Ms[r][c] = xh[r * 64 + c] - xh[c * 64 + r] + (r == c ? 1.0f : 0.0f);
    }
    #pragma unroll
    for (int l = 0; l < 32; l++) {
        int idx = tid + l * 256;
        int r = idx >> 7, c = idx & 127;
        Wc[r][c] = Wo[(size_t)(h * 64 + r) * E + ch * 128 + c];
    }
    __syncthreads();

    const int col = tid & 127;
    const int rh = (tid >> 7) * 32;
    for (int f = 0; f < F; f++) {
        float nw[32];
        #pragma unroll
        for (int r = 0; r < 32; r++) nw[r] = 0.0f;
        #pragma unroll 4
        for (int k = 0; k < 64; k++) {
            float wv = Wc[k][col];
            #pragma unroll
            for (int r = 0; r < 32; r++) nw[r] += Ms[rh + r][k] * wv;
        }
        __syncthreads();
        #pragma unroll
        for (int r = 0; r < 32; r++) {
            Wc[rh + r][col] = nw[r];
            g_weff[((size_t)f * E + h * 64 + rh + r) * E + ch * 128 + col] = nw[r];
        }
        __syncthreads();
    }
}

// ---------------------------------------------------------------------------
extern "C" void kernel_launch(void* const* d_in, const int* in_sizes, int n_in,
                              void* d_out, int out_size)
{
    (void)in_sizes; (void)n_in; (void)out_size;
    const float* query = (const float*)d_in[0];
    // d_in[1] = key, d_in[2] = value : unused by the reference forward
    const float* Wqkv  = (const float*)d_in[3];
    const float* bqkv  = (const float*)d_in[4];
    const float* Wo    = (const float*)d_in[5];
    const float* bo    = (const float*)d_in[6];
    const float* Xi    = (const float*)d_in[7];
    float* out = (float*)d_out;

    // 1) QKV projection: g_qkv = query @ Wqkv + bqkv
    dim3 g1(E3 / 128, MROWS / 128);
    sgemm128<0><<<g1, 256>>>(query, Wqkv, bqkv, nullptr);

    // 2) causal flash attention -> g_attn (concat-head layout [8192,512])
    flash64<<<dim3(SEQ / 64, H, BATCH), 256>>>();

    // 3) fold SINDy dynamics into output projection: g_weff[f] = M^{f+1} @ Wo
    weff_kernel<<<dim3(E / 128, H), 256>>>(Xi, Wo);

    // 4) out[b,f,s,:] = g_attn @ g_weff[f] + bo
    dim3 g4(E / 128, MROWS / 128, F);
    sgemm128<1><<<g4, 256>>>(nullptr, nullptr, bo, out);
}

// round 5
// speedup vs baseline: 1.2590x; 1.2590x over previous
#include <cuda_runtime.h>
#include <cstdint>
#include <math.h>

// ---------------------------------------------------------------------------
// MultiHeadSINDyAttention — R5: tf32 mma.sync GEMMs (sm_100-base compatible)
//   qkv  = query @ Wqkv + bqkv          (tf32 HMMA: 8192x1536x512)
//   attn = causal flash attention       (fp32 SIMT, 32 heads 2048x64)
//   W_eff[f] = (I+Xi-Xi^T)^{f+1} @ Wo   (tiny; stored transposed [n][k])
//   out[b,f,s,:] = attn @ W_eff[f] + bo (tf32 HMMA: 8x 8192x512x512)
// ---------------------------------------------------------------------------

namespace {
constexpr int BATCH = 4;
constexpr int SEQ   = 2048;
constexpr int E     = 512;
constexpr int E3    = 1536;
constexpr int H     = 8;
constexpr int F     = 8;
constexpr int MROWS = BATCH * SEQ;   // 8192
}

__device__ float g_qkv[MROWS * E3];    // [8192,1536]
__device__ float g_attn[MROWS * E];    // [8192,512]
__device__ float g_weffT[F * E * E];   // [f][n][k]
__device__ float g_WqkvT[E3 * E];      // [n][k]

__device__ __forceinline__ uint32_t f2tf32(float f) {
    uint32_t u;
    asm("cvt.rna.tf32.f32 %0, %1;" : "=r"(u) : "f"(f));
    return u;
}
__device__ __forceinline__ void mma_tf32(float c[4], uint32_t a0, uint32_t a1,
                                         uint32_t a2, uint32_t a3,
                                         uint32_t b0, uint32_t b1) {
    asm volatile(
        "mma.sync.aligned.m16n8k8.row.col.f32.tf32.tf32.f32 "
        "{%0,%1,%2,%3}, {%4,%5,%6,%7}, {%8,%9}, {%0,%1,%2,%3};"
        : "+f"(c[0]), "+f"(c[1]), "+f"(c[2]), "+f"(c[3])
        : "r"(a0), "r"(a1), "r"(a2), "r"(a3), "r"(b0), "r"(b1));
}

// ---------------------------------------------------------------------------
// tf32 HMMA GEMM: C[m,n] = A[m,:] . B[n,:] + bias[n]   (B given as [n][k])
// Block tile 128x128, BK=16, double-buffered.  8 warps = 2(m) x 4(n),
// warp tile 64x32 = 4x4 m16n8k8 fragments.
// MODE 0: A=query, B=g_WqkvT, C=g_qkv (N=1536 row stride)
// MODE 1: A=g_attn, B=g_weffT[z], C=out with [b,f,s,e] row remap
// ---------------------------------------------------------------------------
template<int MODE>
__global__ __launch_bounds__(256, 2)
void gemm_mma(const float* __restrict__ Ain, const float* __restrict__ bias,
              float* __restrict__ Cp)
{
    constexpr int LDS_ = 20;   // padded stride: (m*20+k)%32 conflict-free
    __shared__ float As[2][128][LDS_];
    __shared__ float Bs[2][128][LDS_];

    const int tid  = threadIdx.x;
    const int wid  = tid >> 5, lane = tid & 31;
    const int bm   = blockIdx.y, bn = blockIdx.x;
    const int wm   = wid >> 2;          // 0..1
    const int wn   = wid & 3;           // 0..3

    const float* A = (MODE == 0) ? Ain : g_attn;
    const float* B = (MODE == 0)
        ? (g_WqkvT + (size_t)bn * 128 * E)
        : (g_weffT + (size_t)blockIdx.z * E * E + (size_t)bn * 128 * E);

    // global load mapping: 256 threads, each 2 float4 per matrix per tile
    const int lm = tid >> 1;            // 0..127
    const int lk = (tid & 1) * 8;       // 0 or 8
    const float* Aptr = A + (size_t)(bm * 128 + lm) * E + lk;
    const float* Bptr = B + (size_t)lm * E + lk;

    float acc[4][4][4];
    #pragma unroll
    for (int i = 0; i < 4; i++)
        #pragma unroll
        for (int j = 0; j < 4; j++)
            #pragma unroll
            for (int q = 0; q < 4; q++) acc[i][j][q] = 0.0f;

    // prologue: tile 0
    {
        float4 a0 = *(const float4*)(Aptr);
        float4 a1 = *(const float4*)(Aptr + 4);
        float4 b0 = *(const float4*)(Bptr);
        float4 b1 = *(const float4*)(Bptr + 4);
        *(float4*)&As[0][lm][lk]     = a0;
        *(float4*)&As[0][lm][lk + 4] = a1;
        *(float4*)&Bs[0][lm][lk]     = b0;
        *(float4*)&Bs[0][lm][lk + 4] = b1;
    }
    __syncthreads();

    const int qrow = lane >> 2;         // 0..7
    const int qk   = lane & 3;          // 0..3
    const int nk = E / 16;              // 32 tiles

    for (int kt = 0; kt < nk; kt++) {
        const int buf = kt & 1;
        float4 pa0, pa1, pb0, pb1;
        if (kt + 1 < nk) {
            pa0 = *(const float4*)(Aptr + (kt + 1) * 16);
            pa1 = *(const float4*)(Aptr + (kt + 1) * 16 + 4);
            pb0 = *(const float4*)(Bptr + (kt + 1) * 16);
            pb1 = *(const float4*)(Bptr + (kt + 1) * 16 + 4);
        }
        #pragma unroll
        for (int ks = 0; ks < 2; ks++) {
            const int kb = ks * 8 + qk;
            uint32_t af[4][4];
            #pragma unroll
            for (int mf = 0; mf < 4; mf++) {
                const int r = wm * 64 + mf * 16 + qrow;
                af[mf][0] = f2tf32(As[buf][r][kb]);
                af[mf][1] = f2tf32(As[buf][r + 8][kb]);
                af[mf][2] = f2tf32(As[buf][r][kb + 4]);
                af[mf][3] = f2tf32(As[buf][r + 8][kb + 4]);
            }
            uint32_t bf[4][2];
            #pragma unroll
            for (int nf = 0; nf < 4; nf++) {
                const int c = wn * 32 + nf * 8 + qrow;
                bf[nf][0] = f2tf32(Bs[buf][c][kb]);
                bf[nf][1] = f2tf32(Bs[buf][c][kb + 4]);
            }
            #pragma unroll
            for (int mf = 0; mf < 4; mf++)
                #pragma unroll
                for (int nf = 0; nf < 4; nf++)
                    mma_tf32(acc[mf][nf], af[mf][0], af[mf][1], af[mf][2],
                             af[mf][3], bf[nf][0], bf[nf][1]);
        }
        if (kt + 1 < nk) {
            const int nb = buf ^ 1;
            *(float4*)&As[nb][lm][lk]     = pa0;
            *(float4*)&As[nb][lm][lk + 4] = pa1;
            *(float4*)&Bs[nb][lm][lk]     = pb0;
            *(float4*)&Bs[nb][lm][lk + 4] = pb1;
            __syncthreads();
        }
    }

    // epilogue: c0,c1 -> (row, n..n+1); c2,c3 -> (row+8, n..n+1)
    #pragma unroll
    for (int nf = 0; nf < 4; nf++) {
        const int n = bn * 128 + wn * 32 + nf * 8 + 2 * qk;
        const float2 bv = *(const float2*)(bias + n);
        #pragma unroll
        for (int mf = 0; mf < 4; mf++) {
            const int m0 = bm * 128 + wm * 64 + mf * 16 + qrow;
            #pragma unroll
            for (int half = 0; half < 2; half++) {
                const int m = m0 + half * 8;
                float2 v;
                v.x = acc[mf][nf][half * 2 + 0] + bv.x;
                v.y = acc[mf][nf][half * 2 + 1] + bv.y;
                if (MODE == 0) {
                    *(float2*)(g_qkv + (size_t)m * E3 + n) = v;
                } else {
                    const int b = m >> 11, s = m & 2047;
                    *(float2*)(Cp + (((size_t)b * F + blockIdx.z) * SEQ + s) * E + n) = v;
                }
            }
        }
    }
}

// ---------------------------------------------------------------------------
// Wqkv transpose: g_WqkvT[n][k] = Wqkv[k][n].  block(32,8), grid(48,16)
// ---------------------------------------------------------------------------
__global__ void transposeWqkv(const float* __restrict__ W)
{
    __shared__ float t[32][33];
    const int x  = blockIdx.x * 32 + threadIdx.x;   // n
    const int y0 = blockIdx.y * 32;                 // k base
    #pragma unroll
    for (int i = threadIdx.y; i < 32; i += 8)
        t[i][threadIdx.x] = W[(size_t)(y0 + i) * E3 + x];
    __syncthreads();
    const int nx = blockIdx.x * 32;
    #pragma unroll
    for (int i = threadIdx.y; i < 32; i += 8)
        g_WqkvT[(size_t)(nx + i) * E + y0 + threadIdx.x] = t[threadIdx.x][i];
}

// ---------------------------------------------------------------------------
// Causal flash attention (fp32 SIMT) — unchanged from the passing R2 kernel.
// ---------------------------------------------------------------------------
__global__ __launch_bounds__(256)
void flash64()
{
    __shared__ float Qt[64][64];
    __shared__ float KtPs[64][64];
    __shared__ float Vs[64][64];

    const int qb = blockIdx.x, h = blockIdx.y, b = blockIdx.z;
    const int tid = threadIdx.x, tx = tid & 15, ty = tid >> 4;
    const unsigned FULL = 0xffffffffu;
    const float* base = g_qkv + (size_t)b * SEQ * E3 + h * 64;

    #pragma unroll
    for (int l = 0; l < 4; l++) {
        int idx = tid + l * 256;
        int r = idx >> 4, v = (idx & 15) * 4;
        float4 t = *(const float4*)(base + (size_t)(qb * 64 + r) * E3 + v);
        Qt[v + 0][r] = t.x * 0.125f;
        Qt[v + 1][r] = t.y * 0.125f;
        Qt[v + 2][r] = t.z * 0.125f;
        Qt[v + 3][r] = t.w * 0.125f;
    }

    float mi[4], li[4], o[4][4];
    #pragma unroll
    for (int i = 0; i < 4; i++) {
        mi[i] = -1e30f; li[i] = 0.0f;
        #pragma unroll
        for (int j = 0; j < 4; j++) o[i][j] = 0.0f;
    }

    for (int jb = 0; jb <= qb; jb++) {
        __syncthreads();
        #pragma unroll
        for (int l = 0; l < 4; l++) {
            int idx = tid + l * 256;
            int r = idx >> 4, v = (idx & 15) * 4;
            const float* rp = base + (size_t)(jb * 64 + r) * E3;
            float4 k4 = *(const float4*)(rp + 512 + v);
            KtPs[v + 0][r] = k4.x;
            KtPs[v + 1][r] = k4.y;
            KtPs[v + 2][r] = k4.z;
            KtPs[v + 3][r] = k4.w;
            float4 v4 = *(const float4*)(rp + 1024 + v);
            *(float4*)&Vs[r][v] = v4;
        }
        __syncthreads();

        float s[4][4];
        #pragma unroll
        for (int i = 0; i < 4; i++)
            #pragma unroll
            for (int j = 0; j < 4; j++) s[i][j] = 0.0f;

        #pragma unroll 8
        for (int kk = 0; kk < 64; kk++) {
            float a[4], bb[4];
            *(float4*)a  = *(const float4*)&Qt[kk][ty * 4];
            *(float4*)bb = *(const float4*)&KtPs[kk][tx * 4];
            #pragma unroll
            for (int i = 0; i < 4; i++)
                #pragma unroll
                for (int j = 0; j < 4; j++)
                    s[i][j] += a[i] * bb[j];
        }

        if (jb == qb) {
            #pragma unroll
            for (int i = 0; i < 4; i++)
                #pragma unroll
                for (int j = 0; j < 4; j++)
                    if (tx * 4 + j > ty * 4 + i) s[i][j] = -1e30f;
        }

        __syncthreads();

        #pragma unroll
        for (int i = 0; i < 4; i++) {
            float mx = fmaxf(fmaxf(s[i][0], s[i][1]), fmaxf(s[i][2], s[i][3]));
            #pragma unroll
            for (int off = 8; off; off >>= 1)
                mx = fmaxf(mx, __shfl_xor_sync(FULL, mx, off));
            float mn = fmaxf(mi[i], mx);
            float sc = __expf(mi[i] - mn);
            float rs = 0.0f;
            #pragma unroll
            for (int j = 0; j < 4; j++) {
                float p = __expf(s[i][j] - mn);
                s[i][j] = p;
                rs += p;
            }
            #pragma unroll
            for (int off = 8; off; off >>= 1)
                rs += __shfl_xor_sync(FULL, rs, off);
            li[i] = li[i] * sc + rs;
            mi[i] = mn;
            #pragma unroll
            for (int j = 0; j < 4; j++) o[i][j] *= sc;
            KtPs[ty * 4 + i][tx * 4 + 0] = s[i][0];
            KtPs[ty * 4 + i][tx * 4 + 1] = s[i][1];
            KtPs[ty * 4 + i][tx * 4 + 2] = s[i][2];
            KtPs[ty * 4 + i][tx * 4 + 3] = s[i][3];
        }
        __syncthreads();

        #pragma unroll 8
        for (int kk = 0; kk < 64; kk++) {
            float4 b4 = *(const float4*)&Vs[kk][tx * 4];
            #pragma unroll
            for (int i = 0; i < 4; i++) {
                float a = KtPs[ty * 4 + i][kk];
                o[i][0] += a * b4.x;
                o[i][1] += a * b4.y;
                o[i][2] += a * b4.z;
                o[i][3] += a * b4.w;
            }
        }
    }

    float* op = g_attn + ((size_t)b * SEQ + qb * 64) * E + h * 64;
    #pragma unroll
    for (int i = 0; i < 4; i++) {
        float inv = 1.0f / li[i];
        float4 v = make_float4(o[i][0] * inv, o[i][1] * inv,
                               o[i][2] * inv, o[i][3] * inv);
        *(float4*)(op + (size_t)(ty * 4 + i) * E + tx * 4) = v;
    }
}

// ---------------------------------------------------------------------------
// W_eff: M = I + Xi - Xi^T;  W_{f+1} = M @ W_f starting at Wo.
// Stores TRANSPOSED: g_weffT[f][n][k].  grid(E/128, H), 256 threads.
// Exactly 48KB static smem (16KB Ms + 32KB Wc) — no padding.
// ---------------------------------------------------------------------------
__global__ __launch_bounds__(256)
void weff_kernel(const float* __restrict__ Xi, const float* __restrict__ Wo)
{
    __shared__ float Ms[64][64];
    __shared__ float Wc[64][128];
    const int h = blockIdx.y, ch = blockIdx.x;
    const int tid = threadIdx.x;
    const float* xh = Xi + h * 64 * 64;

    #pragma unroll
    for (int l = 0; l < 16; l++) {
        int idx = tid + l * 256;
        int r = idx >> 6, c = idx & 63;
        Ms[r][c] = xh[r * 64 + c] - xh[c * 64 + r] + (r == c ? 1.0f : 0.0f);
    }
    #pragma unroll
    for (int l = 0; l < 32; l++) {
        int idx = tid + l * 256;
        int r = idx >> 7, c = idx & 127;
        Wc[r][c] = Wo[(size_t)(h * 64 + r) * E + ch * 128 + c];
    }
    __syncthreads();

    const int col = tid & 127;
    const int rh = (tid >> 7) * 32;
    for (int f = 0; f < F; f++) {
        float nw[32];
        #pragma unroll
        for (int r = 0; r < 32; r++) nw[r] = 0.0f;
        #pragma unroll 4
        for (int k = 0; k < 64; k++) {
            float wv = Wc[k][col];
            #pragma unroll
            for (int r = 0; r < 32; r++) nw[r] += Ms[rh + r][k] * wv;
        }
        __syncthreads();
        #pragma unroll
        for (int r = 0; r < 32; r++) Wc[rh + r][col] = nw[r];
        __syncthreads();
        // transposed coalesced store: g_weffT[f][n][k] (bank conflicts on the
        // strided smem read are fine — this kernel is ~1% of runtime)
        #pragma unroll
        for (int l = 0; l < 32; l++) {
            int idx = tid + l * 256;
            int nl = idx >> 6;
            int kl = idx & 63;
            g_weffT[((size_t)f * E + ch * 128 + nl) * E + h * 64 + kl] = Wc[kl][nl];
        }
        __syncthreads();
    }
}

// ---------------------------------------------------------------------------
extern "C" void kernel_launch(void* const* d_in, const int* in_sizes, int n_in,
                              void* d_out, int out_size)
{
    (void)in_sizes; (void)n_in; (void)out_size;
    const float* query = (const float*)d_in[0];
    const float* Wqkv  = (const float*)d_in[3];
    const float* bqkv  = (const float*)d_in[4];
    const float* Wo    = (const float*)d_in[5];
    const float* bo    = (const float*)d_in[6];
    const float* Xi    = (const float*)d_in[7];
    float* out = (float*)d_out;

    // weight prep (tiny, independent)
    transposeWqkv<<<dim3(E3 / 32, E / 32), dim3(32, 8)>>>(Wqkv);
    weff_kernel<<<dim3(E / 128, H), 256>>>(Xi, Wo);

    // 1) QKV projection (tf32 HMMA)
    gemm_mma<0><<<dim3(E3 / 128, MROWS / 128), 256>>>(query, bqkv, nullptr);

    // 2) causal flash attention -> g_attn
    flash64<<<dim3(SEQ / 64, H, BATCH), 256>>>();

    // 3) out[b,f,s,:] = g_attn @ W_eff[f]^T + bo  (tf32 HMMA)
    gemm_mma<1><<<dim3(E / 128, MROWS / 128, F), 256>>>(nullptr, bo, out);
}